// round 14
// baseline (speedup 1.0000x reference)
#include <cuda_runtime.h>
#include <cuda_bf16.h>

// T=4096, B=512, n=32, deg=3. Sequential nonlinear RNN over T.
//
// R14 = R10 (best, 552us) + latency-model-driven changes:
//   MODEL (fits R9..R13): kernel is LATENCY-bound at ~253 cyc/step =
//   12(update) + 124(pinned serial sum) + 12(poly) + ~105(df tanh spine);
//   tanh runs nearly every step with poly in the saturated band (~5..9.2].
//   1. fast tanh for x in (4.75, 9.2]: th = 1 - 2/(e^{2x}+1) via MUFU ex2 +
//      low-word correction + MUFU rcp. abs err ~7.5e-11 << df's 1e-9 (which
//      was already bit-identical to fp64). ~60-cyc chain vs 105. Computed
//      every step, branch-free; df kept under a ballot for rare (0,4.75].
//   2. w-precompute: w = fma(dec,v,mul(cur,a)) hoisted off the fs-chain
//      (same rounded ops, R11-validated order) -> update chain 12 -> 8.
//   3. single-lane layout (R12/R13 proved shuffles only add latency).
// Checksum: rel_err must be exactly 0.0001636959.

static constexpr int BATCH  = 512;
static constexpr int NSTATE = 32;
static constexpr int PF     = 8;   // ring depth == unroll factor

// Double-float tanh for x in (0, 4.75] (transition zone; verbatim from R10).
__device__ __forceinline__ float tanh_df_lean(float x) {
    const float t  = 2.0f * x;
    const float kf = rintf(t * 1.4426950408889634f);
    const int   ki = (int)kf;

    const float L_h = 0.693147182464599609375f;
    const float L_l = -1.9046542996577634e-9f;
    const float ph = kf * L_h;
    const float pe = fmaf(kf, L_h, -ph);
    const float d  = t - ph;
    const float rh = d - pe;
    const float bb = rh - d;
    const float er = (d - (rh - bb)) + (-pe - bb);
    const float rl = er - kf * L_l;

    const float r2h = rh * rh;
    float r2l = fmaf(rh, rh, -r2h);
    r2l = fmaf(2.0f * rh, rl, r2l);

    float C = fmaf(rh, 2.4801587302e-5f, 1.9841269841e-4f);
    C = fmaf(rh, C, 1.3888888889e-3f);
    C = fmaf(rh, C, 8.3333333333e-3f);
    C = fmaf(rh, C, 4.1666666667e-2f);
    C = fmaf(rh, C, 1.6666666667e-1f);
    const float cub = (r2h * rh) * C;

    const float q  = 0.5f * r2h;
    float mh = rh + q;
    float ml = (rh - mh) + q;
    ml = ml + (cub + (rl + 0.5f * r2l));
    { const float s = mh + ml; ml = ml - (s - mh); mh = s; }

    const float pk = __int_as_float((ki + 127) << 23);
    const float ah = pk * mh;
    const float al = fmaf(pk, ml, fmaf(pk, mh, -ah));

    const float n1 = pk - 1.0f;
    const float nd = n1 - pk;
    const float ne = (pk - (n1 - nd)) + (-1.0f - nd);
    const float nh = n1 + ah;
    const float tb1 = nh - n1;
    const float nl = ((n1 - (nh - tb1)) + (ah - tb1)) + ne + al;

    const float d1 = pk + 1.0f;
    const float dd = d1 - pk;
    const float de = (pk - (d1 - dd)) + (1.0f - dd);
    const float dh = d1 + ah;
    const float tb2 = dh - d1;
    const float dl = ((d1 - (dh - tb2)) + (ah - tb2)) + de + al;

    float rcp;
    asm("rcp.approx.f32 %0, %1;" : "=f"(rcp) : "f"(dh));
    const float q0 = nh * rcp;
    const float e1 = fmaf(-q0, dh, nh);
    const float resid = e1 + fmaf(-q0, dl, nl);
    return fmaf(resid, rcp, q0);
}

__global__ void __launch_bounds__(32, 1)
rnn_firing_rate_r14(const float* __restrict__ currents,   // [T, B]
                    const float* __restrict__ a_vec,      // [n]
                    const float* __restrict__ b_vec,      // [n]
                    const float* __restrict__ ds,         // [n]
                    const float* __restrict__ poly_coeff, // [4]
                    const float* __restrict__ g_b,        // [1]
                    float* __restrict__ out,              // [T, B]
                    int T)
{
    const int batch = blockIdx.x * 32 + threadIdx.x;

    float av[NSTATE], bv[NSTATE], dec[NSTATE], v[NSTATE], w[NSTATE];
    #pragma unroll
    for (int k = 0; k < NSTATE; ++k) {
        av[k]  = a_vec[k];
        bv[k]  = b_vec[k];
        dec[k] = 1.0f - ds[k];
        v[k]   = 0.0f;
    }
    const float c0 = poly_coeff[0] * poly_coeff[0];
    const float c1 = poly_coeff[1] * poly_coeff[1];
    const float c2 = poly_coeff[2] * poly_coeff[2];
    const float c3 = poly_coeff[3] * poly_coeff[3];
    const float gbv = g_b[0];

    // current prefetch ring — static indices via unroll => registers
    float cbuf[PF];
    #pragma unroll
    for (int i = 0; i < PF; ++i)
        cbuf[i] = (i < T) ? currents[i * BATCH + batch] : 0.0f;

    // prologue: w for t=0 (v=0): identical rounded ops to the validated
    // pattern m=mul(cur,a); w=fma(dec,v,m)
    #pragma unroll
    for (int k = 0; k < NSTATE; ++k)
        w[k] = __fmaf_rn(dec[k], v[k], __fmul_rn(cbuf[0], av[k]));

    const float* cptr = currents + (size_t)PF * BATCH + batch;
    float*       optr = out + batch;

    float fs = 0.0f;

    for (int tblk = 0; tblk < T; tblk += PF) {
        #pragma unroll
        for (int u = 0; u < PF; ++u) {
            const int t = tblk + u;
            if (t + PF < T) cbuf[u] = cptr[u * BATCH];  // refill slot u -> cur(t+8)

            const float h = __fmul_rn(1000.0f, fs);

            // v[k] = fma(h, b[k], w[k]) — only ONE fma on the fs-chain.
            // natural-order sequential sum (pinned).
            float s = 0.0f;
            #pragma unroll
            for (int k = 0; k < NSTATE; ++k) {
                v[k] = __fmaf_rn(h, bv[k], w[k]);
                s += v[k];
            }

            // z = mean(v) - g_b ; poly (verbatim R10 expressions)
            const float z  = s * (1.0f / 32.0f) - gbv;
            const float z2 = z * z;
            const float z3 = z2 * z;
            const float poly = c0 + c1 * z + c2 * z2 + c3 * z3;

            // fast tanh (valid & used for poly in (4.75, 9.2]); branch-free.
            // th = 1 - 2/(E+1), E = 2^(poly*2log2e) w/ low-word correction.
            const float wh = __fmul_rn(poly, 2.8853900432586670f);
            float wl = fmaf(poly, 2.8853900432586670f, -wh);
            wl = fmaf(poly, 3.8519259985e-8f, wl);
            float E0; asm("ex2.approx.f32 %0, %1;" : "=f"(E0) : "f"(wh));
            const float E = fmaf(E0, __fmul_rn(wl, 0.6931471805599453f), E0);
            const float D = E + 1.0f;
            float rd; asm("rcp.approx.f32 %0, %1;" : "=f"(rd) : "f"(D));
            float th = fmaf(-2.0f, rd, 1.0f);

            // df override for the rare transition zone (0, 4.75]
            const bool lo = (poly > 0.0f) && (poly <= 4.75f);
            if (__ballot_sync(0xFFFFFFFFu, lo)) {
                const float th_lo = tanh_df_lean(poly);
                th = lo ? th_lo : th;
            }

            // fs = relu(100*tanh) with exact clip zones (verbatim selects)
            const float fsv = fmaxf(100.0f * th, 0.0f);
            fs = (poly <= 0.0f) ? 0.0f : ((poly > 9.2f) ? 100.0f : fsv);

            *optr = fs;
            optr += BATCH;

            // w for step t+1 from cur(t+1) — off the fs-chain; same rounded
            // ops/order as the validated pattern.
            const float cnext = cbuf[(u + 1) & (PF - 1)];
            #pragma unroll
            for (int k = 0; k < NSTATE; ++k)
                w[k] = __fmaf_rn(dec[k], v[k], __fmul_rn(cnext, av[k]));
        }
        cptr += PF * BATCH;
    }
}

extern "C" void kernel_launch(void* const* d_in, const int* in_sizes, int n_in,
                              void* d_out, int out_size)
{
    const float* currents   = (const float*)d_in[0];  // [T*B]
    const float* a_vec      = (const float*)d_in[1];  // [32]
    const float* b_vec      = (const float*)d_in[2];  // [32]
    const float* ds         = (const float*)d_in[3];  // [32]
    const float* poly_coeff = (const float*)d_in[4];  // [4]
    const float* g_b        = (const float*)d_in[5];  // [1]
    float* out = (float*)d_out;

    const int T = in_sizes[0] / BATCH;                // 4096

    rnn_firing_rate_r14<<<BATCH / 32, 32>>>(currents, a_vec, b_vec, ds,
                                            poly_coeff, g_b, out, T);
}